// round 13
// baseline (speedup 1.0000x reference)
#include <cuda_runtime.h>
#include <cuda_fp16.h>
#include <cstdint>

#define LOG2E 1.4426950408889634f

// ---------------- scratch (device globals; no allocations allowed) ----------
__device__ float    g_part[8 * 64];           // per (b,c) partial sums
__device__ float    g_t[64];                  // relu(MLP) * log2(e)
__device__ uint32_t g_Wh[64 * 25 * 8];        // half2 weights [c][tap][8 slots]
__device__ float    g_bc[9 * 25];             // per-tap bias [k][tap]
__device__ float    g_B[225];                 // bias case table [k][hcase][wcase]
__device__ float    g_wt[8 * 9 * 128 * 128];  // conv logits [b][k][h][w]

__device__ __forceinline__ __half2 u2h(uint32_t u) {
    return *reinterpret_cast<__half2*>(&u);
}

// ---------------- P1: chansum (0..511) + weights (512..561) + bias (562) ----
__global__ void k_prep1(const float* __restrict__ x, const float* __restrict__ w1,
                        const float* __restrict__ b1, const float* __restrict__ w2) {
    int blk = blockIdx.x;
    int tid = threadIdx.x;   // 256
    if (blk < 512) {
        int c = blk & 63, b = blk >> 6;
        const float4* p = (const float4*)(x + (size_t)(b * 64 + c) * 16384);
        float s0 = 0.f, s1 = 0.f, s2 = 0.f, s3 = 0.f;
        #pragma unroll
        for (int i = 0; i < 16; ++i) {
            float4 v = p[tid + i * 256];
            s0 += v.x; s1 += v.y; s2 += v.z; s3 += v.w;
        }
        float s = (s0 + s1) + (s2 + s3);
        __shared__ float sh[256];
        sh[tid] = s;
        __syncthreads();
        for (int o = 128; o > 0; o >>= 1) {
            if (tid < o) sh[tid] += sh[tid + o];
            __syncthreads();
        }
        if (tid == 0) g_part[b * 64 + c] = sh[0];
    } else if (blk < 562) {
        int idx = (blk - 512) * 256 + tid;       // 0..12799
        if (idx < 12800) {
            int c = idx / 200, rem = idx % 200;
            int tap = rem / 8, slot = rem % 8;
            float f0 = 0.f, f1 = 0.f;
            if (slot < 5) {
                int k0 = (slot < 4) ? 2 * slot : 8;
                int k1 = (slot < 4) ? 2 * slot + 1 : 8;
                #pragma unroll 8
                for (int o = 0; o < 64; ++o) {
                    float wo = w1[o * 64 + c];
                    f0 += w2[(k0 * 64 + o) * 25 + tap] * wo;
                    f1 += w2[(k1 * 64 + o) * 25 + tap] * wo;
                }
            }
            __half2 h = __floats2half2_rn(f0, f1);   // low = f0 (even k)
            g_Wh[idx] = *reinterpret_cast<uint32_t*>(&h);
        }
    } else {
        if (tid < 225) {
            int k = tid / 25, tap = tid % 25;
            float s = 0.f;
            #pragma unroll 8
            for (int o = 0; o < 64; ++o)
                s += w2[(k * 64 + o) * 25 + tap] * b1[o];
            g_bc[tid] = s;
        }
    }
}

// ---------------- P2: single block: bias case table + MLP -------------------
__global__ void k_prep2(const float* __restrict__ tc1, const float* __restrict__ tc2) {
    __shared__ float smean[64];
    __shared__ float sh1[16];
    int tid = threadIdx.x;   // 256
    if (tid < 64) {
        float s = 0.f;
        #pragma unroll
        for (int b = 0; b < 8; ++b) s += g_part[b * 64 + tid];
        smean[tid] = s * (1.f / 131072.f);
    }
    // bias case table: case a for h (0,1 -> h; 3,4 -> h-123; 2 -> interior)
    if (tid < 225) {
        int k = tid / 25, r = tid % 25;
        int a = r / 5, bb = r % 5;
        int ylo = (2 - a > 0) ? 2 - a : 0, yhi = (6 - a < 4) ? 6 - a : 4;
        int xlo = (2 - bb > 0) ? 2 - bb : 0, xhi = (6 - bb < 4) ? 6 - bb : 4;
        float s = 0.f;
        for (int dy = ylo; dy <= yhi; ++dy)
            for (int dx = xlo; dx <= xhi; ++dx)
                s += g_bc[k * 25 + dy * 5 + dx];
        g_B[tid] = s;
    }
    __syncthreads();
    if (tid < 16) {
        float a = 0.f;
        #pragma unroll
        for (int c = 0; c < 64; ++c) a += tc1[tid * 64 + c] * smean[c];
        sh1[tid] = fmaxf(a, 0.f);
    }
    __syncthreads();
    if (tid < 64) {
        float a = 0.f;
        #pragma unroll
        for (int j = 0; j < 16; ++j) a += tc2[tid * 16 + j] * sh1[j];
        g_t[tid] = fmaxf(a, 0.f) * LOG2E;
    }
}

// ---------------- kernel D: 5x5 conv, HFMA2, 32x8 tiles, double buffered ----
// Grid (4,16,8) = 512 CTAs; block (32,4); thread owns 2 consecutive rows.
// Dynamic smem (40448 B): sW[2][1600] u32; sX[2][3456] u32 (8c x 12 x 36).
__global__ void __launch_bounds__(128) k_conv(const float* __restrict__ x) {
    extern __shared__ uint32_t sdyn[];
    uint32_t* sWs = sdyn;            // 2 x 1600
    uint32_t* sXs = sdyn + 3200;     // 2 x 3456
    __shared__ float sB[225];
    int tx = threadIdx.x, ty = threadIdx.y;
    int tid = ty * 32 + tx;
    int h0 = blockIdx.y * 8, w0 = blockIdx.x * 32;
    int bz = blockIdx.z;
    const float* xb = x + (size_t)bz * 64 * 16384;

    // 128 threads -> strided load of the 225-entry table (R12 bug: tid<225)
    for (int i = tid; i < 225; i += 128) sB[i] = g_B[i];

    __half2 acc[2][4], acc8;
    #pragma unroll
    for (int j = 0; j < 2; ++j)
        #pragma unroll
        for (int p = 0; p < 4; ++p) acc[j][p] = __floats2half2_rn(0.f, 0.f);
    acc8 = __floats2half2_rn(0.f, 0.f);

    // --- stage chunk 0 into buffer 0 ---
    #pragma unroll
    for (int it = 0; it < 13; ++it) {
        int i = tid + it * 128;
        if (i < 1600) sWs[i] = g_Wh[i];
    }
    #pragma unroll
    for (int it = 0; it < 27; ++it) {
        int i = tid + it * 128;
        int c = i / 432, rem = i % 432;
        int y = rem / 36, xx = rem % 36;
        int gh = h0 + y - 2, gw = w0 + xx - 2;
        float v = 0.f;
        if (gh >= 0 && gh < 128 && gw >= 0 && gw < 128)
            v = xb[(size_t)c * 16384 + gh * 128 + gw];
        __half2 hv = __float2half2_rn(v);
        sXs[i] = *reinterpret_cast<uint32_t*>(&hv);
    }
    __syncthreads();

    #pragma unroll 1
    for (int ch = 0; ch < 8; ++ch) {
        int cur = ch & 1;
        if (ch < 7) {
            int nb = cur ^ 1;
            int cb = (ch + 1) * 8;
            #pragma unroll
            for (int it = 0; it < 13; ++it) {
                int i = tid + it * 128;
                if (i < 1600) sWs[nb * 1600 + i] = g_Wh[cb * 200 + i];
            }
            #pragma unroll
            for (int it = 0; it < 27; ++it) {
                int i = tid + it * 128;
                int c = i / 432, rem = i % 432;
                int y = rem / 36, xx = rem % 36;
                int gh = h0 + y - 2, gw = w0 + xx - 2;
                float v = 0.f;
                if (gh >= 0 && gh < 128 && gw >= 0 && gw < 128)
                    v = xb[(size_t)(cb + c) * 16384 + gh * 128 + gw];
                __half2 hv = __float2half2_rn(v);
                sXs[nb * 3456 + i] = *reinterpret_cast<uint32_t*>(&hv);
            }
        }
        #pragma unroll 1
        for (int c = 0; c < 8; ++c) {
            const uint32_t* xbase = sXs + cur * 3456 + c * 432 + (ty * 2) * 36 + tx;
            uint32_t xw[6][5];
            #pragma unroll
            for (int r = 0; r < 6; ++r)
                #pragma unroll
                for (int q = 0; q < 5; ++q)
                    xw[r][q] = xbase[r * 36 + q];

            const uint32_t* wc = sWs + cur * 1600 + c * 200;
            #pragma unroll
            for (int dy = 0; dy < 5; ++dy) {
                #pragma unroll
                for (int dx = 0; dx < 5; ++dx) {
                    int tap = dy * 5 + dx;
                    uint4 wv = *reinterpret_cast<const uint4*>(wc + tap * 8);
                    uint32_t p4 = wc[tap * 8 + 4];
                    __half2 w0h = u2h(wv.x), w1h = u2h(wv.y),
                            w2h = u2h(wv.z), w3h = u2h(wv.w);
                    uint32_t xa = xw[dy][dx];
                    uint32_t xb2 = xw[dy + 1][dx];
                    __half2 ha = u2h(xa), hb = u2h(xb2);
                    acc[0][0] = __hfma2(w0h, ha, acc[0][0]);
                    acc[0][1] = __hfma2(w1h, ha, acc[0][1]);
                    acc[0][2] = __hfma2(w2h, ha, acc[0][2]);
                    acc[0][3] = __hfma2(w3h, ha, acc[0][3]);
                    acc[1][0] = __hfma2(w0h, hb, acc[1][0]);
                    acc[1][1] = __hfma2(w1h, hb, acc[1][1]);
                    acc[1][2] = __hfma2(w2h, hb, acc[1][2]);
                    acc[1][3] = __hfma2(w3h, hb, acc[1][3]);
                    uint32_t xab = __byte_perm(xa, xb2, 0x5410);   // {a.lo, b.lo}
                    acc8 = __hfma2(u2h(p4), u2h(xab), acc8);
                }
            }
        }
        __syncthreads();
    }

    int w = w0 + tx;
    int cw = (w < 2) ? w : ((w > 125) ? (w - 123) : 2);
    #pragma unroll
    for (int j = 0; j < 2; ++j) {
        int h = h0 + ty * 2 + j;
        int pix = h * 128 + w;
        int chc = (h < 2) ? h : ((h > 125) ? (h - 123) : 2);
        float v[9];
        #pragma unroll
        for (int p = 0; p < 4; ++p) {
            v[2 * p]     = __low2float(acc[j][p]);
            v[2 * p + 1] = __high2float(acc[j][p]);
        }
        v[8] = j ? __high2float(acc8) : __low2float(acc8);
        #pragma unroll
        for (int k = 0; k < 9; ++k)
            g_wt[((size_t)bz * 9 + k) * 16384 + pix] = v[k] + sB[k * 25 + chc * 5 + cw];
    }
}

// ---------------- kernel E: softmax + gather, smem-staged patches -----------
// Grid (64, 8, 8): (row pair, batch, channel eighth). 128 threads, 2 px each.
// Stage 4 rows x 130 cols (incl reflect halo) per channel, double buffered.
__global__ void __launch_bounds__(128) k_out(const float* __restrict__ x,
                                             float* __restrict__ out) {
    __shared__ float st[64];
    __shared__ float sx[2][4][132];
    int w = threadIdx.x;
    int h = blockIdx.x * 2;
    int b = blockIdx.y;
    int ce = blockIdx.z;
    if (w < 64) st[w] = g_t[w];

    int rows4[4];
    rows4[0] = (h == 0) ? 1 : h - 1;
    rows4[1] = h;
    rows4[2] = h + 1;
    rows4[3] = (h + 1 == 127) ? 126 : h + 2;

    float ak0[9], ak1[9];
    float M0 = -1e30f, M1 = -1e30f;
    #pragma unroll
    for (int k = 0; k < 9; ++k) {
        size_t i0 = ((size_t)b * 9 + k) * 16384 + h * 128 + w;
        float a0 = g_wt[i0], a1 = g_wt[i0 + 128];
        ak0[k] = a0; M0 = fmaxf(M0, a0);
        ak1[k] = a1; M1 = fmaxf(M1, a1);
    }
    #pragma unroll
    for (int k = 0; k < 9; ++k) { ak0[k] -= M0; ak1[k] -= M1; }

    const float* xb = x + (size_t)b * 64 * 16384;
    int cbeg = ce * 8;

    // stage channel cbeg into buffer 0
    {
        const float* xc = xb + (size_t)cbeg * 16384;
        #pragma unroll
        for (int r = 0; r < 4; ++r) sx[0][r][w + 1] = xc[rows4[r] * 128 + w];
        if (w < 4) sx[0][w][0] = xc[rows4[w] * 128 + 1];          // reflect(-1)=1
        else if (w < 8) sx[0][w - 4][129] = xc[rows4[w - 4] * 128 + 126]; // reflect(128)=126
    }
    __syncthreads();

    #pragma unroll 1
    for (int i = 0; i < 8; ++i) {
        int cur = i & 1;
        if (i < 7) {
            const float* xc = xb + (size_t)(cbeg + i + 1) * 16384;
            int nb = cur ^ 1;
            #pragma unroll
            for (int r = 0; r < 4; ++r) sx[nb][r][w + 1] = xc[rows4[r] * 128 + w];
            if (w < 4) sx[nb][w][0] = xc[rows4[w] * 128 + 1];
            else if (w < 8) sx[nb][w - 4][129] = xc[rows4[w - 4] * 128 + 126];
        }
        int c = cbeg + i;
        float t = st[c];
        float g[4][3];
        #pragma unroll
        for (int r = 0; r < 4; ++r) {
            g[r][0] = sx[cur][r][w];
            g[r][1] = sx[cur][r][w + 1];
            g[r][2] = sx[cur][r][w + 2];
        }
        float o0, o1;
        if (t == 0.f) {
            float sA = (g[0][0] + g[0][1]) + g[0][2];
            float sB2 = (g[1][0] + g[1][1]) + g[1][2];
            float sC = (g[2][0] + g[2][1]) + g[2][2];
            float sD = (g[3][0] + g[3][1]) + g[3][2];
            o0 = (sA + sB2 + sC) * (1.f / 9.f);
            o1 = (sB2 + sC + sD) * (1.f / 9.f);
        } else {
            float s0 = 0.f, oo0 = 0.f, s1 = 0.f, oo1 = 0.f;
            #pragma unroll
            for (int k = 0; k < 9; ++k) {
                float e0, e1;
                asm("ex2.approx.ftz.f32 %0, %1;" : "=f"(e0) : "f"(ak0[k] * t));
                asm("ex2.approx.ftz.f32 %0, %1;" : "=f"(e1) : "f"(ak1[k] * t));
                s0 += e0; oo0 = fmaf(e0, g[k / 3][k % 3], oo0);
                s1 += e1; oo1 = fmaf(e1, g[k / 3 + 1][k % 3], oo1);
            }
            o0 = __fdividef(oo0, s0);
            o1 = __fdividef(oo1, s1);
        }
        size_t obase = (size_t)(b * 64 + c) * 16384 + h * 128 + w;
        out[obase] = o0;
        out[obase + 128] = o1;
        __syncthreads();
    }
}

// ---------------- launch ----------------------------------------------------
extern "C" void kernel_launch(void* const* d_in, const int* in_sizes, int n_in,
                              void* d_out, int out_size) {
    const float* x   = (const float*)d_in[0];
    const float* w1  = (const float*)d_in[1];
    const float* b1  = (const float*)d_in[2];
    const float* w2  = (const float*)d_in[3];
    const float* tc1 = (const float*)d_in[4];
    const float* tc2 = (const float*)d_in[5];
    float* out = (float*)d_out;
    (void)in_sizes; (void)n_in; (void)out_size;

    static bool attr_set = false;
    if (!attr_set) {
        cudaFuncSetAttribute(k_conv, cudaFuncAttributeMaxDynamicSharedMemorySize, 40448);
        attr_set = true;
    }

    k_prep1<<<563, 256>>>(x, w1, b1, w2);
    k_prep2<<<1, 256>>>(tc1, tc2);
    dim3 gc(4, 16, 8), bc(32, 4);
    k_conv<<<gc, bc, 40448>>>(x);
    dim3 ge(64, 8, 8);
    k_out<<<ge, 128>>>(x, out);
}